// round 2
// baseline (speedup 1.0000x reference)
#include <cuda_runtime.h>
#include <cstdint>
#include <cstddef>

#define TT   2048
#define BB   64
#define NIN  128
#define HH   256
#define NOUT 128
#define MROWS (TT * BB)   // 131072

// Device-global scratch (allocation-free rule)
__device__ __align__(16) float g_xp[(size_t)TT * BB * HH];  // 128 MB
__device__ __align__(16) float g_hs[(size_t)TT * BB * HH];  // 128 MB

// ---------- packed fp32 helpers ----------
__device__ __forceinline__ unsigned long long fma2(unsigned long long a,
                                                   unsigned long long b,
                                                   unsigned long long c) {
    unsigned long long d;
    asm("fma.rn.f32x2 %0, %1, %2, %3;" : "=l"(d) : "l"(a), "l"(b), "l"(c));
    return d;
}
__device__ __forceinline__ float red2(unsigned long long a) {
    float lo, hi;
    asm("mov.b64 {%0, %1}, %2;" : "=f"(lo), "=f"(hi) : "l"(a));
    return lo + hi;
}

// =====================================================================
// K1: g_xp[row][h] = dot(x[row][:], w_ih[h][:]) + b_ih[h] + b_hh[h]
// 256 threads, thread = output channel h. 32 rows per block.
// =====================================================================
__global__ void __launch_bounds__(256, 1) k_inproj(const float* __restrict__ x,
                                                   const float* __restrict__ w_ih,
                                                   const float* __restrict__ b_ih,
                                                   const float* __restrict__ b_hh) {
    __shared__ __align__(16) float xs[32 * NIN];  // 16 KB
    const int t = threadIdx.x;
    const int row0 = blockIdx.x * 32;

    // register-resident weight row (128 floats)
    ulonglong2 w[32];
    {
        const ulonglong2* wr = (const ulonglong2*)(w_ih + (size_t)t * NIN);
#pragma unroll
        for (int i = 0; i < 32; i++) w[i] = wr[i];
    }
    const float bias = b_ih[t] + b_hh[t];

    // stage 32 contiguous rows of x (4096 floats)
    {
        const float4* src = (const float4*)(x + (size_t)row0 * NIN);
        float4* dst = (float4*)xs;
#pragma unroll
        for (int i = t; i < 32 * NIN / 4; i += 256) dst[i] = src[i];
    }
    __syncthreads();

    for (int m = 0; m < 32; m++) {
        const ulonglong2* xr = (const ulonglong2*)(xs + m * NIN);
        unsigned long long a0 = 0ull, a1 = 0ull, a2 = 0ull, a3 = 0ull;
#pragma unroll
        for (int i = 0; i < 32; i += 2) {
            ulonglong2 v0 = xr[i];
            ulonglong2 v1 = xr[i + 1];
            a0 = fma2(w[i].x, v0.x, a0);
            a1 = fma2(w[i].y, v0.y, a1);
            a2 = fma2(w[i + 1].x, v1.x, a2);
            a3 = fma2(w[i + 1].y, v1.y, a3);
        }
        g_xp[(size_t)(row0 + m) * HH + t] =
            (red2(a0) + red2(a1)) + (red2(a2) + red2(a3)) + bias;
    }
}

// =====================================================================
// K2: recurrent scan. 1 CTA per batch element (64 CTAs), 256 threads,
// thread j owns h[j]; w_hh row j (256 floats) register-resident.
// h double-buffered in smem, reads are warp-uniform broadcasts.
// =====================================================================
__global__ void __launch_bounds__(256, 1) k_scan(const float* __restrict__ w_hh) {
    __shared__ __align__(16) float hbuf[2][HH];

    const int j = threadIdx.x;
    const int b = blockIdx.x;

    // register-resident weight row: 256 floats = 64 ulonglong2 = 128 regs
    ulonglong2 w[64];
    {
        const ulonglong2* wr = (const ulonglong2*)(w_hh + (size_t)j * HH);
#pragma unroll
        for (int i = 0; i < 64; i++) w[i] = wr[i];
    }

    hbuf[0][j] = 0.0f;
    hbuf[1][j] = 0.0f;
    __syncthreads();

    const size_t STRIDE = (size_t)BB * HH;
    const float* xp_ptr = g_xp + (size_t)b * HH + j;
    float* hs_ptr = g_hs + (size_t)b * HH + j;

    float xp_cur = __ldg(xp_ptr);
    xp_ptr += STRIDE;

    for (int tt = 0; tt < TT; tt++) {
        // prefetch next step's xp so DRAM latency hides under the FMA wall
        float xp_nxt = 0.0f;
        if (tt + 1 < TT) xp_nxt = __ldg(xp_ptr);
        xp_ptr += STRIDE;

        const int p = tt & 1;  // write buffer
        const ulonglong2* hr = (const ulonglong2*)(hbuf[p ^ 1]);

        unsigned long long a0 = 0ull, a1 = 0ull, a2 = 0ull, a3 = 0ull;
#pragma unroll
        for (int i = 0; i < 64; i += 2) {
            ulonglong2 v0 = hr[i];      // uniform address -> broadcast
            ulonglong2 v1 = hr[i + 1];
            a0 = fma2(w[i].x, v0.x, a0);
            a1 = fma2(w[i].y, v0.y, a1);
            a2 = fma2(w[i + 1].x, v1.x, a2);
            a3 = fma2(w[i + 1].y, v1.y, a3);
        }
        float h = tanhf(xp_cur + (red2(a0) + red2(a1)) + (red2(a2) + red2(a3)));

        hbuf[p][j] = h;
        hs_ptr[0] = h;         // streamed out; fire-and-forget
        hs_ptr += STRIDE;
        xp_cur = xp_nxt;
        __syncthreads();       // one barrier/step (double buffer)
    }
}

// =====================================================================
// K3: out[row][o] = dot(g_hs[row][:], w_out[o][:]) + b_out[o]
// 256 threads: o = t&127, half = t>>7 picks 32-row subgroup. 64 rows/block.
// =====================================================================
__global__ void __launch_bounds__(256, 1) k_outproj(const float* __restrict__ w_out,
                                                    const float* __restrict__ b_out,
                                                    float* __restrict__ out) {
    __shared__ __align__(16) float hs[64 * HH];  // 64 KB
    const int t = threadIdx.x;
    const int o = t & 127;
    const int half = t >> 7;
    const int row0 = blockIdx.x * 64;

    ulonglong2 w[64];  // w_out row o: 256 floats
    {
        const ulonglong2* wr = (const ulonglong2*)(w_out + (size_t)o * HH);
#pragma unroll
        for (int i = 0; i < 64; i++) w[i] = wr[i];
    }
    const float bias = b_out[o];

    // stage 64 contiguous rows of hs (16384 floats)
    {
        const float4* src = (const float4*)(g_hs + (size_t)row0 * HH);
        float4* dst = (float4*)hs;
#pragma unroll
        for (int i = t; i < 64 * HH / 4; i += 256) dst[i] = src[i];
    }
    __syncthreads();

    const int mbase = half * 32;
    for (int m = 0; m < 32; m++) {
        const ulonglong2* hr = (const ulonglong2*)(hs + (mbase + m) * HH);
        unsigned long long a0 = 0ull, a1 = 0ull, a2 = 0ull, a3 = 0ull;
#pragma unroll
        for (int i = 0; i < 64; i += 2) {
            ulonglong2 v0 = hr[i];
            ulonglong2 v1 = hr[i + 1];
            a0 = fma2(w[i].x, v0.x, a0);
            a1 = fma2(w[i].y, v0.y, a1);
            a2 = fma2(w[i + 1].x, v1.x, a2);
            a3 = fma2(w[i + 1].y, v1.y, a3);
        }
        out[(size_t)(row0 + mbase + m) * NOUT + o] =
            (red2(a0) + red2(a1)) + (red2(a2) + red2(a3)) + bias;
    }
}

// =====================================================================
extern "C" void kernel_launch(void* const* d_in, const int* in_sizes, int n_in,
                              void* d_out, int out_size) {
    const float* x     = (const float*)d_in[0];
    const float* w_ih  = (const float*)d_in[1];
    const float* w_hh  = (const float*)d_in[2];
    const float* b_ih  = (const float*)d_in[3];
    const float* b_hh  = (const float*)d_in[4];
    const float* w_out = (const float*)d_in[5];
    const float* b_out = (const float*)d_in[6];
    float* out = (float*)d_out;

    k_inproj<<<MROWS / 32, 256>>>(x, w_ih, b_ih, b_hh);
    k_scan<<<BB, 256>>>(w_hh);
    k_outproj<<<MROWS / 64, 256>>>(w_out, b_out, out);
}

// round 8
// speedup vs baseline: 2.0393x; 2.0393x over previous
#include <cuda_runtime.h>
#include <cstdint>
#include <cstddef>

#define TT   2048
#define BB   64
#define NIN  128
#define HH   256
#define NOUT 128
#define MROWS (TT * BB)   // 131072

__device__ __align__(16) float g_xp[(size_t)TT * BB * HH];  // 128 MB
__device__ __align__(16) float g_hs[(size_t)TT * BB * HH];  // 128 MB

__device__ __forceinline__ unsigned long long fma2(unsigned long long a,
                                                   unsigned long long b,
                                                   unsigned long long c) {
    unsigned long long d;
    asm("fma.rn.f32x2 %0, %1, %2, %3;" : "=l"(d) : "l"(a), "l"(b), "l"(c));
    return d;
}
__device__ __forceinline__ float red2(unsigned long long a) {
    float lo, hi;
    asm("mov.b64 {%0, %1}, %2;" : "=f"(lo), "=f"(hi) : "l"(a));
    return lo + hi;
}
__device__ __forceinline__ uint32_t smem_u32(const void* p) {
    uint32_t a;
    asm("{ .reg .u64 t; cvta.to.shared.u64 t, %1; cvt.u32.u64 %0, t; }" : "=r"(a) : "l"(p));
    return a;
}
__device__ __forceinline__ void mbar_init(uint32_t addr, uint32_t cnt) {
    asm volatile("mbarrier.init.shared.b64 [%0], %1;" :: "r"(addr), "r"(cnt) : "memory");
}
__device__ __forceinline__ uint32_t mapa_u32(uint32_t addr, uint32_t rank) {
    uint32_t r;
    asm("mapa.shared::cluster.u32 %0, %1, %2;" : "=r"(r) : "r"(addr), "r"(rank));
    return r;
}
__device__ __forceinline__ void st_remote_f32(uint32_t addr, float v) {
    asm volatile("st.shared::cluster.f32 [%0], %1;" :: "r"(addr), "f"(v) : "memory");
}
__device__ __forceinline__ void arrive_remote(uint32_t addr) {
    asm volatile("mbarrier.arrive.release.cluster.shared::cluster.b64 _, [%0];"
                 :: "r"(addr) : "memory");
}
__device__ __forceinline__ void mbar_wait(uint32_t addr, int parity) {
    asm volatile(
        "{\n\t.reg .pred P;\n\t"
        "WL%=:\n\t"
        "mbarrier.try_wait.parity.acquire.cluster.shared::cta.b64 P, [%0], %1, 0x989680;\n\t"
        "@P bra WD%=;\n\t"
        "bra WL%=;\n\t"
        "WD%=:\n\t}"
        :: "r"(addr), "r"(parity) : "memory");
}
__device__ __forceinline__ void cluster_sync_() {
    asm volatile("barrier.cluster.arrive.aligned;" ::: "memory");
    asm volatile("barrier.cluster.wait.aligned;" ::: "memory");
}

// =====================================================================
// K1/K3 unified projection: C[M x O] = A[M x K] * W[O x K]^T + bias
// 512 threads: o = tid % O, g = tid / O (split-k). Weight chunk (64
// floats) register-resident. 64 rows/block, double-buffered staging.
// =====================================================================
template<int O, int K, bool TWOB>
__global__ void __launch_bounds__(512, 1)
k_proj(const float* __restrict__ A, const float* __restrict__ W,
       const float* __restrict__ bias1, const float* __restrict__ bias2,
       float* __restrict__ C) {
    constexpr int G   = 512 / O;
    constexpr int KT  = K / G;       // 64
    constexpr int KT4 = KT / 4;      // 16
    constexpr int RPB = 64;
    constexpr int RG  = 8;
    constexpr int NGR = RPB / RG;
    constexpr int NLD = RG * K / 4;

    __shared__ __align__(16) float stage[2][RG * K];
    __shared__ float scr[2][G - 1][RG][O];

    const int tid = threadIdx.x;
    const int o = tid % O;
    const int g = tid / O;
    const size_t m0 = (size_t)blockIdx.x * RPB;

    ulonglong2 w[KT4];
    {
        const ulonglong2* wr = (const ulonglong2*)(W + (size_t)o * K + g * KT);
#pragma unroll
        for (int i = 0; i < KT4; i++) w[i] = wr[i];
    }
    const float bias = TWOB ? (bias1[o] + bias2[o]) : bias1[o];

    float4 ld = make_float4(0.f, 0.f, 0.f, 0.f);
    if (tid < NLD) ld = __ldg(((const float4*)(A + m0 * K)) + tid);

    for (int grp = 0; grp < NGR; grp++) {
        const int buf = grp & 1;
        if (tid < NLD) ((float4*)stage[buf])[tid] = ld;
        __syncthreads();
        if (grp + 1 < NGR && tid < NLD)
            ld = __ldg(((const float4*)(A + (m0 + (size_t)(grp + 1) * RG) * K)) + tid);

        float pr[RG];
#pragma unroll
        for (int r = 0; r < RG; r++) {
            const ulonglong2* xr = (const ulonglong2*)(stage[buf] + r * K + g * KT);
            unsigned long long a0 = 0ull, a1 = 0ull;
#pragma unroll
            for (int i = 0; i < KT4; i++) {
                ulonglong2 v = xr[i];
                a0 = fma2(w[i].x, v.x, a0);
                a1 = fma2(w[i].y, v.y, a1);
            }
            pr[r] = red2(a0) + red2(a1);
        }
        if (g) {
#pragma unroll
            for (int r = 0; r < RG; r++) scr[buf][g - 1][r][o] = pr[r];
        }
        __syncthreads();
        if (!g) {
#pragma unroll
            for (int r = 0; r < RG; r++) {
                float s = pr[r] + bias;
#pragma unroll
                for (int q = 0; q < G - 1; q++) s += scr[buf][q][r][o];
                C[(m0 + (size_t)grp * RG + r) * O + o] = s;
            }
        }
    }
}

// =====================================================================
// K2: recurrent scan. Cluster of 2 CTAs per batch (128 CTAs).
// CTA rank owns 128 outputs; 256 threads = (jj in [0,128)) x (g in {0,1}).
// g covers k-half: g=0 -> locally produced half (no wait), g=1 -> peer
// half (mbarrier wait). Weights: 128 floats register-resident.
// h exchanged via DSMEM stores + per-writer release-arrive.
// =====================================================================
__global__ void __cluster_dims__(2, 1, 1) __launch_bounds__(256, 1)
k_scan(const float* __restrict__ w_hh) {
    __shared__ __align__(16) float hbuf[2][HH];
    __shared__ float scr[128];
    __shared__ __align__(8) unsigned long long mbar[2];

    const int tid = threadIdx.x;
    const int jj = tid & 127;
    const int g = tid >> 7;
    const int rank = blockIdx.x & 1;
    const int b = blockIdx.x >> 1;
    const int j = rank * 128 + jj;
    const int kbase = (g ? (rank ^ 1) : rank) * 128;

    ulonglong2 w[32];
    {
        const ulonglong2* wr = (const ulonglong2*)(w_hh + (size_t)j * HH + kbase);
#pragma unroll
        for (int i = 0; i < 32; i++) w[i] = wr[i];
    }

    for (int i = tid; i < 2 * HH; i += 256) ((float*)hbuf)[i] = 0.0f;
    if (tid == 0) { mbar_init(smem_u32(&mbar[0]), 128); mbar_init(smem_u32(&mbar[1]), 128); }
    __syncthreads();
    cluster_sync_();   // peer mbars initialized, hbufs zeroed

    const uint32_t peer = rank ^ 1;
    const uint32_t rem_m0 = mapa_u32(smem_u32(&mbar[0]), peer);
    const uint32_t rem_m1 = mapa_u32(smem_u32(&mbar[1]), peer);
    const uint32_t rem_h0 = mapa_u32(smem_u32(&hbuf[0][j]), peer);
    const uint32_t rem_h1 = mapa_u32(smem_u32(&hbuf[1][j]), peer);
    const uint32_t loc_m0 = smem_u32(&mbar[0]);
    const uint32_t loc_m1 = smem_u32(&mbar[1]);

    // pre-arrival so the first read of hbuf[1] (zeros) passes its wait
    if (!g) arrive_remote(rem_m1);

    const size_t STRIDE = (size_t)BB * HH;
    const float* xp_ptr = g_xp + (size_t)b * HH + j;
    float* hs_ptr = g_hs + (size_t)b * HH + j;
    float xp_cur = 0.0f, xp_nxt = 0.0f;
    if (!g) { xp_cur = __ldg(xp_ptr); xp_ptr += STRIDE; }

    int ph0 = 0, ph1 = 0;

    for (int tt = 0; tt < TT; tt++) {
        const int p = tt & 1;      // write buffer
        const int rp = p ^ 1;      // read buffer
        if (g) {
            if (rp) { mbar_wait(loc_m1, ph1); ph1 ^= 1; }
            else    { mbar_wait(loc_m0, ph0); ph0 ^= 1; }
        }
        const ulonglong2* hr = (const ulonglong2*)(&hbuf[rp][kbase]);
        unsigned long long a0 = 0ull, a1 = 0ull, a2 = 0ull, a3 = 0ull;
#pragma unroll
        for (int i = 0; i < 32; i += 2) {
            ulonglong2 v0 = hr[i];
            ulonglong2 v1 = hr[i + 1];
            a0 = fma2(w[i].x, v0.x, a0);
            a1 = fma2(w[i].y, v0.y, a1);
            a2 = fma2(w[i + 1].x, v1.x, a2);
            a3 = fma2(w[i + 1].y, v1.y, a3);
        }
        float part = (red2(a0) + red2(a1)) + (red2(a2) + red2(a3));
        if (g) scr[jj] = part;
        __syncthreads();                                   // bar A
        if (!g) {
            if (tt + 1 < TT) xp_nxt = __ldg(xp_ptr);
            xp_ptr += STRIDE;
            float h = tanhf(part + scr[jj] + xp_cur);
            hbuf[p][j] = h;                                // local copy
            st_remote_f32(p ? rem_h1 : rem_h0, h);         // peer copy (DSMEM)
            arrive_remote(p ? rem_m1 : rem_m0);            // release-arrive
            xp_cur = xp_nxt;
        }
        __syncthreads();                                   // bar B
        if (g) {                                           // g=1 drains to HBM
            *hs_ptr = hbuf[p][j];
            hs_ptr += STRIDE;
        }
    }
    cluster_sync_();   // don't tear down smem while peer stores in flight
}

// =====================================================================
extern "C" void kernel_launch(void* const* d_in, const int* in_sizes, int n_in,
                              void* d_out, int out_size) {
    const float* x     = (const float*)d_in[0];
    const float* w_ih  = (const float*)d_in[1];
    const float* w_hh  = (const float*)d_in[2];
    const float* b_ih  = (const float*)d_in[3];
    const float* b_hh  = (const float*)d_in[4];
    const float* w_out = (const float*)d_in[5];
    const float* b_out = (const float*)d_in[6];
    float* out = (float*)d_out;

    float *xp, *hs;
    cudaGetSymbolAddress((void**)&xp, g_xp);
    cudaGetSymbolAddress((void**)&hs, g_hs);

    k_proj<HH, NIN, true><<<MROWS / 64, 512>>>(x, w_ih, b_ih, b_hh, xp);
    k_scan<<<2 * BB, 256>>>(w_hh);
    k_proj<NOUT, HH, false><<<MROWS / 64, 512>>>(hs, w_out, b_out, b_out, out);
}

// round 10
// speedup vs baseline: 2.8878x; 1.4160x over previous
#include <cuda_runtime.h>
#include <cstdint>
#include <cstddef>

#define TT   2048
#define BB   64
#define NIN  128
#define HH   256
#define NOUT 128
#define MROWS (TT * BB)   // 131072

__device__ __align__(16) float g_xp[(size_t)TT * BB * HH];  // 128 MB
__device__ __align__(16) float g_hs[(size_t)TT * BB * HH];  // 128 MB

__device__ __forceinline__ unsigned long long fma2(unsigned long long a,
                                                   unsigned long long b,
                                                   unsigned long long c) {
    unsigned long long d;
    asm("fma.rn.f32x2 %0, %1, %2, %3;" : "=l"(d) : "l"(a), "l"(b), "l"(c));
    return d;
}
__device__ __forceinline__ float red2(unsigned long long a) {
    float lo, hi;
    asm("mov.b64 {%0, %1}, %2;" : "=f"(lo), "=f"(hi) : "l"(a));
    return lo + hi;
}
__device__ __forceinline__ uint32_t smem_u32(const void* p) {
    uint32_t a;
    asm("{ .reg .u64 t; cvta.to.shared.u64 t, %1; cvt.u32.u64 %0, t; }" : "=r"(a) : "l"(p));
    return a;
}
__device__ __forceinline__ void mbar_init(uint32_t addr, uint32_t cnt) {
    asm volatile("mbarrier.init.shared.b64 [%0], %1;" :: "r"(addr), "r"(cnt) : "memory");
}
__device__ __forceinline__ void mbar_arm_tx(uint32_t addr, uint32_t bytes) {
    asm volatile("mbarrier.arrive.expect_tx.shared.b64 _, [%0], %1;"
                 :: "r"(addr), "r"(bytes) : "memory");
}
__device__ __forceinline__ uint32_t mapa_u32(uint32_t addr, uint32_t rank) {
    uint32_t r;
    asm("mapa.shared::cluster.u32 %0, %1, %2;" : "=r"(r) : "r"(addr), "r"(rank));
    return r;
}
// fused remote store + tx-complete signal on the remote mbarrier
__device__ __forceinline__ void st_async_f32(uint32_t addr, float v, uint32_t mbar) {
    asm volatile("st.async.shared::cluster.mbarrier::complete_tx::bytes.b32 [%0], %1, [%2];"
                 :: "r"(addr), "r"(__float_as_uint(v)), "r"(mbar) : "memory");
}
__device__ __forceinline__ void mbar_wait(uint32_t addr, int parity) {
    asm volatile(
        "{\n\t.reg .pred P;\n\t"
        "WL%=:\n\t"
        "mbarrier.try_wait.parity.acquire.cluster.shared::cta.b64 P, [%0], %1, 0x989680;\n\t"
        "@P bra WD%=;\n\t"
        "bra WL%=;\n\t"
        "WD%=:\n\t}"
        :: "r"(addr), "r"(parity) : "memory");
}
__device__ __forceinline__ void cluster_sync_() {
    asm volatile("barrier.cluster.arrive.aligned;" ::: "memory");
    asm volatile("barrier.cluster.wait.aligned;" ::: "memory");
}
// tanh(x) = 1 - 2/(exp(2x)+1), MUFU-based (~45 cyc, abs err ~1e-6)
__device__ __forceinline__ float fast_tanh(float x) {
    float e, r;
    float t = x * 2.8853900817779268f;      // 2*log2(e)
    asm("ex2.approx.f32 %0, %1;" : "=f"(e) : "f"(t));
    float d = e + 1.0f;
    asm("rcp.approx.f32 %0, %1;" : "=f"(r) : "f"(d));
    return fmaf(-2.0f, r, 1.0f);
}

// =====================================================================
// K1/K3 unified projection: C[M x O] = A[M x K] * W[O x K]^T + bias
// =====================================================================
template<int O, int K, bool TWOB>
__global__ void __launch_bounds__(512, 1)
k_proj(const float* __restrict__ A, const float* __restrict__ W,
       const float* __restrict__ bias1, const float* __restrict__ bias2,
       float* __restrict__ C) {
    constexpr int G   = 512 / O;
    constexpr int KT  = K / G;       // 64
    constexpr int KT4 = KT / 4;      // 16
    constexpr int RPB = 64;
    constexpr int RG  = 8;
    constexpr int NGR = RPB / RG;
    constexpr int NLD = RG * K / 4;

    __shared__ __align__(16) float stage[2][RG * K];
    __shared__ float scr[2][G - 1][RG][O];

    const int tid = threadIdx.x;
    const int o = tid % O;
    const int g = tid / O;
    const size_t m0 = (size_t)blockIdx.x * RPB;

    ulonglong2 w[KT4];
    {
        const ulonglong2* wr = (const ulonglong2*)(W + (size_t)o * K + g * KT);
#pragma unroll
        for (int i = 0; i < KT4; i++) w[i] = wr[i];
    }
    const float bias = TWOB ? (bias1[o] + bias2[o]) : bias1[o];

    float4 ld = make_float4(0.f, 0.f, 0.f, 0.f);
    if (tid < NLD) ld = __ldg(((const float4*)(A + m0 * K)) + tid);

    for (int grp = 0; grp < NGR; grp++) {
        const int buf = grp & 1;
        if (tid < NLD) ((float4*)stage[buf])[tid] = ld;
        __syncthreads();
        if (grp + 1 < NGR && tid < NLD)
            ld = __ldg(((const float4*)(A + (m0 + (size_t)(grp + 1) * RG) * K)) + tid);

        float pr[RG];
#pragma unroll
        for (int r = 0; r < RG; r++) {
            const ulonglong2* xr = (const ulonglong2*)(stage[buf] + r * K + g * KT);
            unsigned long long a0 = 0ull, a1 = 0ull;
#pragma unroll
            for (int i = 0; i < KT4; i++) {
                ulonglong2 v = xr[i];
                a0 = fma2(w[i].x, v.x, a0);
                a1 = fma2(w[i].y, v.y, a1);
            }
            pr[r] = red2(a0) + red2(a1);
        }
        if (g) {
#pragma unroll
            for (int r = 0; r < RG; r++) scr[buf][g - 1][r][o] = pr[r];
        }
        __syncthreads();
        if (!g) {
#pragma unroll
            for (int r = 0; r < RG; r++) {
                float s = pr[r] + bias;
#pragma unroll
                for (int q = 0; q < G - 1; q++) s += scr[buf][q][r][o];
                C[(m0 + (size_t)grp * RG + r) * O + o] = s;
            }
        }
    }
}

// =====================================================================
// K2: recurrent scan. Cluster of 2 CTAs per batch (128 CTAs).
// 256 threads = (jj in [0,128)) x (g in {0,1}). g=0: local k-half +
// finalize; g=1: peer k-half (mbarrier wait). Weights register-resident.
// h exchange: st.async (data + tx-complete fused); mbar count=1, armed
// consumer-side with expect_tx(512B) once per phase.
// =====================================================================
__global__ void __cluster_dims__(2, 1, 1) __launch_bounds__(256, 1)
k_scan(const float* __restrict__ w_hh) {
    __shared__ __align__(16) float hbuf[2][HH];
    __shared__ float scr[2][128];
    __shared__ __align__(8) unsigned long long mbar[2];

    const int tid = threadIdx.x;
    const int jj = tid & 127;
    const int g = tid >> 7;
    const int rank = blockIdx.x & 1;
    const int b = blockIdx.x >> 1;
    const int j = rank * 128 + jj;
    const int kbase = (g ? (rank ^ 1) : rank) * 128;

    ulonglong2 w[32];
    {
        const ulonglong2* wr = (const ulonglong2*)(w_hh + (size_t)j * HH + kbase);
#pragma unroll
        for (int i = 0; i < 32; i++) w[i] = wr[i];
    }

    for (int i = tid; i < 2 * HH; i += 256) ((float*)hbuf)[i] = 0.0f;
    const uint32_t loc_m0 = smem_u32(&mbar[0]);
    const uint32_t loc_m1 = smem_u32(&mbar[1]);
    if (tid == 0) {
        mbar_init(loc_m0, 1);
        mbar_init(loc_m1, 1);
        mbar_arm_tx(loc_m0, 512);   // phase 0 of both buffers pre-armed
        mbar_arm_tx(loc_m1, 512);
    }
    __syncthreads();
    cluster_sync_();   // peer mbars armed, hbufs zeroed before any st.async

    const uint32_t peer = rank ^ 1;
    const uint32_t rem_m0 = mapa_u32(loc_m0, peer);
    const uint32_t rem_m1 = mapa_u32(loc_m1, peer);
    const uint32_t rem_h0 = mapa_u32(smem_u32(&hbuf[0][j]), peer);
    const uint32_t rem_h1 = mapa_u32(smem_u32(&hbuf[1][j]), peer);

    const size_t STRIDE = (size_t)BB * HH;
    const float* xp_ptr = g_xp + (size_t)b * HH + j;
    float* hs_ptr = g_hs + (size_t)b * HH + j;

    // 4-deep xp prefetch ring (g=0 only) — hides DRAM latency fully
    float x0 = 0.f, x1 = 0.f, x2 = 0.f, x3 = 0.f;
    if (!g) {
        x0 = __ldg(xp_ptr);
        x1 = __ldg(xp_ptr + STRIDE);
        x2 = __ldg(xp_ptr + 2 * STRIDE);
        x3 = __ldg(xp_ptr + 3 * STRIDE);
        xp_ptr += 4 * STRIDE;
    }

    int ph0 = 0, ph1 = 0;

    for (int tt = 0; tt < TT; tt++) {
        const int p = tt & 1;      // write buffer
        const int rp = p ^ 1;      // read buffer

        float xp_use = 0.f;
        if (!g) {                  // rotate ring; issue prefetch early
            xp_use = x0;
            x0 = x1; x1 = x2; x2 = x3;
            x3 = (tt + 4 < TT) ? __ldg(xp_ptr) : 0.f;
            xp_ptr += STRIDE;
        } else {                   // wait for peer half of h(t-1)
            if (rp == 0) {
                mbar_wait(loc_m0, ph0); ph0 ^= 1;
                if (tid == 128) mbar_arm_tx(loc_m0, 512);  // arm next phase
            } else if (tt) {
                mbar_wait(loc_m1, ph1); ph1 ^= 1;
                if (tid == 128) mbar_arm_tx(loc_m1, 512);
            }                      // tt==0: hbuf[1] holds zeros, no wait
        }

        const ulonglong2* hr = (const ulonglong2*)(&hbuf[rp][kbase]);
        unsigned long long a0 = 0ull, a1 = 0ull, a2 = 0ull, a3 = 0ull;
#pragma unroll
        for (int i = 0; i < 32; i += 2) {
            ulonglong2 v0 = hr[i];
            ulonglong2 v1 = hr[i + 1];
            a0 = fma2(w[i].x, v0.x, a0);
            a1 = fma2(w[i].y, v0.y, a1);
            a2 = fma2(w[i + 1].x, v1.x, a2);
            a3 = fma2(w[i + 1].y, v1.y, a3);
        }
        float part = (red2(a0) + red2(a1)) + (red2(a2) + red2(a3));
        if (g) scr[p][jj] = part;
        __syncthreads();                                   // bar A
        if (!g) {
            float h = fast_tanh(part + scr[p][jj] + xp_use);
            st_async_f32(p ? rem_h1 : rem_h0, h, p ? rem_m1 : rem_m0);  // send first
            hbuf[p][j] = h;                                // local copy
            *hs_ptr = h;                                   // HBM stream
            hs_ptr += STRIDE;
        }
        __syncthreads();                                   // bar B
    }

    // drain: peer's tt=2047 stores (buffer 1) land before teardown
    if (tid == 128) mbar_wait(loc_m1, ph1);
    cluster_sync_();
}

// =====================================================================
extern "C" void kernel_launch(void* const* d_in, const int* in_sizes, int n_in,
                              void* d_out, int out_size) {
    const float* x     = (const float*)d_in[0];
    const float* w_ih  = (const float*)d_in[1];
    const float* w_hh  = (const float*)d_in[2];
    const float* b_ih  = (const float*)d_in[3];
    const float* b_hh  = (const float*)d_in[4];
    const float* w_out = (const float*)d_in[5];
    const float* b_out = (const float*)d_in[6];
    float* out = (float*)d_out;

    float *xp, *hs;
    cudaGetSymbolAddress((void**)&xp, g_xp);
    cudaGetSymbolAddress((void**)&hs, g_hs);

    k_proj<HH, NIN, true><<<MROWS / 64, 512>>>(x, w_ih, b_ih, b_hh, xp);
    k_scan<<<2 * BB, 256>>>(w_hh);
    k_proj<NOUT, HH, false><<<MROWS / 64, 512>>>(hs, w_out, b_out, b_out, out);
}